// round 16
// baseline (speedup 1.0000x reference)
#include <cuda_runtime.h>
#include <math.h>
#include <stdint.h>

#define BS     32
#define GRID_N 2704
#define A_N    3
#define CH     85
#define VDIM   1024
#define HDIM   512
#define SEL    32
#define ROWS   (BS * SEL)          // 1024 flattened rows
#define EPSF   1e-8f

// ---------------- device scratch (static, no allocation) ----------------
__device__ int      g_idx[BS * SEL];
__device__ uint32_t g_iselH[(size_t)ROWS * (VDIM / 2)];   // packed bf16 hi pairs
__device__ uint32_t g_iselL[(size_t)ROWS * (VDIM / 2)];   // packed bf16 lo pairs
__device__ float    g_vis[(size_t)ROWS * HDIM];
__device__ float    g_vis2[(size_t)ROWS * HDIM];
__device__ float    g_lang[BS * HDIM];
__device__ float    g_ln[BS];
// presplit weights (packed bf16 pairs along K)
__device__ uint32_t g_WvsH[(size_t)(VDIM / 2) * HDIM];
__device__ uint32_t g_WvsL[(size_t)(VDIM / 2) * HDIM];
__device__ uint32_t g_WcH[(size_t)HDIM * HDIM];           // [Wvp ; Wtg] concat pairs
__device__ uint32_t g_WcL[(size_t)HDIM * HDIM];
// presplit gated activations for gemm2: [vis*w0 | tag*w1] concat pairs
__device__ uint32_t g_XYH[(size_t)ROWS * HDIM];
__device__ uint32_t g_XYL[(size_t)ROWS * HDIM];

// ---------------- bf16 split helpers --------------------------------------
__device__ __forceinline__ uint32_t pack_bf16x2(float lo, float hi) {
    uint32_t r;
    asm("cvt.rn.bf16x2.f32 %0, %1, %2;" : "=r"(r) : "f"(hi), "f"(lo));
    return r;
}
__device__ __forceinline__ void split_pair(float x0, float x1, uint32_t& hp, uint32_t& lp) {
    hp = pack_bf16x2(x0, x1);
    float h0 = __uint_as_float(hp << 16);
    float h1 = __uint_as_float(hp & 0xFFFF0000u);
    lp = pack_bf16x2(x0 - h0, x1 - h1);
}
__device__ __forceinline__ void mma16(float d[4], const uint32_t a[4], const uint32_t b[2]) {
    asm volatile(
        "mma.sync.aligned.m16n8k16.row.col.f32.bf16.bf16.f32 "
        "{%0,%1,%2,%3}, {%4,%5,%6,%7}, {%8,%9}, {%0,%1,%2,%3};"
        : "+f"(d[0]), "+f"(d[1]), "+f"(d[2]), "+f"(d[3])
        : "r"(a[0]), "r"(a[1]), "r"(a[2]), "r"(a[3]), "r"(b[0]), "r"(b[1]));
}

// ---------------- K0: presplit weights + lang projection -----------------
// blocks 0..511: weight splits. blocks 512..543: lang proj + norm (input-only dep).
__global__ __launch_bounds__(256) void wsplit_kernel(const float* __restrict__ Wvs,
                                                     const float* __restrict__ Wvp,
                                                     const float* __restrict__ Wtg,
                                                     const float* __restrict__ lang,
                                                     const float* __restrict__ Wts,
                                                     const float* __restrict__ bts) {
    if (blockIdx.x >= 512) {
        // ---- language projection: one block per batch ----
        int b = blockIdx.x - 512;
        int tid = threadIdx.x;                   // 256 threads, 2 outputs each
        __shared__ float lg[HDIM];
        __shared__ float red[256];
        lg[tid] = lang[b * HDIM + tid];
        lg[tid + 256] = lang[b * HDIM + tid + 256];
        __syncthreads();
        int h0 = tid, h1 = tid + 256;
        float a0 = bts[h0], a1 = bts[h1];
        #pragma unroll 8
        for (int k = 0; k < HDIM; k++) {
            float l = lg[k];
            a0 += l * Wts[(size_t)k * HDIM + h0];
            a1 += l * Wts[(size_t)k * HDIM + h1];
        }
        g_lang[b * HDIM + h0] = a0;
        g_lang[b * HDIM + h1] = a1;
        red[tid] = a0 * a0 + a1 * a1;
        __syncthreads();
        for (int o = 128; o; o >>= 1) {
            if (tid < o) red[tid] += red[tid + o];
            __syncthreads();
        }
        if (tid == 0) g_ln[b] = sqrtf(red[0]) + EPSF;
        return;
    }
    int i = blockIdx.x * 256 + threadIdx.x;   // 0 .. 131071
    if (i < 65536) {
        int p = i >> 7;                       // pair row 0..511 (VDIM/2)
        int n4 = (i & 127) * 4;
        float4 r0 = *(const float4*)&Wvs[(size_t)(2 * p) * HDIM + n4];
        float4 r1 = *(const float4*)&Wvs[(size_t)(2 * p + 1) * HDIM + n4];
        uint4 h, l;
        split_pair(r0.x, r1.x, h.x, l.x);
        split_pair(r0.y, r1.y, h.y, l.y);
        split_pair(r0.z, r1.z, h.z, l.z);
        split_pair(r0.w, r1.w, h.w, l.w);
        *(uint4*)&g_WvsH[(size_t)p * HDIM + n4] = h;
        *(uint4*)&g_WvsL[(size_t)p * HDIM + n4] = l;
    } else {
        int j = i - 65536;
        int p = j >> 7;                       // concat pair row 0..511
        int n4 = (j & 127) * 4;
        const float* W = (p < 256) ? Wvp : Wtg;
        int pp = (p < 256) ? p : p - 256;
        float4 r0 = *(const float4*)&W[(size_t)(2 * pp) * HDIM + n4];
        float4 r1 = *(const float4*)&W[(size_t)(2 * pp + 1) * HDIM + n4];
        uint4 h, l;
        split_pair(r0.x, r1.x, h.x, l.x);
        split_pair(r0.y, r1.y, h.y, l.y);
        split_pair(r0.z, r1.z, h.z, l.z);
        split_pair(r0.w, r1.w, h.w, l.w);
        *(uint4*)&g_WcH[(size_t)p * HDIM + n4] = h;
        *(uint4*)&g_WcL[(size_t)p * HDIM + n4] = l;
    }
}

// ---------------- K1: objectness score + exact top-32 via histogram ------
__global__ void topk_kernel(const float* __restrict__ boxes) {
    int b = blockIdx.x;
    int tid = threadIdx.x;          // 256 threads
    __shared__ float sc[GRID_N];
    __shared__ int   hist[512];
    __shared__ int   s_binB, s_definite;
    __shared__ int   cnt_hi, cnt_cb, overflow;
    __shared__ int   hi_idx[SEL];
    __shared__ float cb_sc[512];
    __shared__ int   cb_idx[512];
    __shared__ int   sel[SEL];
    __shared__ float rv[8];
    __shared__ int   ri[8];

    for (int i = tid; i < 512; i += 256) hist[i] = 0;
    if (tid == 0) { cnt_hi = 0; cnt_cb = 0; overflow = 0; }
    __syncthreads();

    const float* bb = boxes + (size_t)b * GRID_N * A_N * CH;
    for (int g = tid; g < GRID_N; g += 256) {
        const float* p = bb + (size_t)g * A_N * CH;
        float s = (p[4] + p[CH + 4] + p[2 * CH + 4]) * (1.0f / 3.0f);
        sc[g] = s;
        int bin = (int)(s * 512.0f);
        bin = max(0, min(511, bin));
        atomicAdd(&hist[bin], 1);
    }
    __syncthreads();

    if (tid == 0) {
        int cum = 0, bB = 0, def = 0;
        for (int v = 511; v >= 0; v--) {
            cum += hist[v];
            if (cum >= SEL) { bB = v; def = cum - hist[v]; break; }
        }
        s_binB = bB; s_definite = def;
    }
    __syncthreads();
    int binB = s_binB;

    for (int g = tid; g < GRID_N; g += 256) {
        float s = sc[g];
        int bin = (int)(s * 512.0f);
        bin = max(0, min(511, bin));
        if (bin > binB) {
            int p = atomicAdd(&cnt_hi, 1);
            hi_idx[p] = g;
        } else if (bin == binB) {
            int p = atomicAdd(&cnt_cb, 1);
            if (p < 512) { cb_sc[p] = s; cb_idx[p] = g; }
            else overflow = 1;
        }
    }
    __syncthreads();

    if (!overflow) {
        if (tid >= 32 && (tid - 32) < s_definite) sel[tid - 32] = hi_idx[tid - 32];
        if (tid < 32) {
            int need = SEL - s_definite;
            int n = min(cnt_cb, 512);
            for (int it = 0; it < need; it++) {
                float best = -1e30f; int bi = GRID_N;
                for (int c = tid; c < n; c += 32) {
                    float v = cb_sc[c]; int gi = cb_idx[c];
                    if (v > best || (v == best && gi < bi)) { best = v; bi = gi; }
                }
                #pragma unroll
                for (int o = 16; o; o >>= 1) {
                    float ov = __shfl_down_sync(0xffffffffu, best, o);
                    int   oi = __shfl_down_sync(0xffffffffu, bi, o);
                    if (ov > best || (ov == best && oi < bi)) { best = ov; bi = oi; }
                }
                bi = __shfl_sync(0xffffffffu, bi, 0);
                if (tid == 0) sel[s_definite + it] = bi;
                for (int c = tid; c < n; c += 32)
                    if (cb_idx[c] == bi) cb_sc[c] = -1e30f;
                __syncwarp();
            }
        }
    }
    __syncthreads();

    if (overflow) {
        for (int it = 0; it < SEL; it++) {
            float best = -1e30f;
            int   bi = GRID_N;
            for (int g = tid; g < GRID_N; g += 256) {
                float v = sc[g];
                if (v > best) { best = v; bi = g; }
            }
            #pragma unroll
            for (int o = 16; o; o >>= 1) {
                float ov = __shfl_down_sync(0xffffffffu, best, o);
                int   oi = __shfl_down_sync(0xffffffffu, bi, o);
                if (ov > best || (ov == best && oi < bi)) { best = ov; bi = oi; }
            }
            if ((tid & 31) == 0) { rv[tid >> 5] = best; ri[tid >> 5] = bi; }
            __syncthreads();
            if (tid == 0) {
                float B = rv[0]; int BI = ri[0];
                for (int w = 1; w < 8; w++)
                    if (rv[w] > B || (rv[w] == B && ri[w] < BI)) { B = rv[w]; BI = ri[w]; }
                sel[it] = BI;
                sc[BI] = -1e30f;
            }
            __syncthreads();
        }
    }

    if (tid == 0) {
        for (int i = 1; i < SEL; i++) {
            int v = sel[i], j = i - 1;
            while (j >= 0 && sel[j] > v) { sel[j + 1] = sel[j]; j--; }
            sel[j + 1] = v;
        }
        for (int i = 0; i < SEL; i++) g_idx[b * SEL + i] = sel[i];
    }
}

// ---------------- K2: gather + pack-split selected feature columns -------
__global__ void gather_kernel(const float* __restrict__ xfeat) {
    int row = blockIdx.x;           // b*SEL + s
    int b = row >> 5;
    int g = g_idx[row];
    const float* src = xfeat + (size_t)b * VDIM * GRID_N + g;
    uint32_t* dh = g_iselH + (size_t)row * (VDIM / 2);
    uint32_t* dl = g_iselL + (size_t)row * (VDIM / 2);
    for (int p = threadIdx.x; p < VDIM / 2; p += blockDim.x) {
        float x0 = __ldg(&src[(size_t)(2 * p) * GRID_N]);
        float x1 = __ldg(&src[(size_t)(2 * p + 1) * GRID_N]);
        uint32_t hp, lp;
        split_pair(x0, x1, hp, lp);
        dh[p] = hp;
        dl[p] = lp;
    }
}

// ============ GEMM skeleton: block 32(M)x64(N), BK=64 (32 pairs), 8 warps =
#define AST 36

// ---------------- K3: vis = isel @ W_vs + b_vs (3x bf16) -----------------
#define G1_NT (VDIM / 64)
__global__ __launch_bounds__(256) void gemm1_kernel(const float* __restrict__ bias) {
    int mBase = blockIdx.y * 32;
    int nBase = blockIdx.x * 64;
    int tid = threadIdx.x;
    int warp = tid >> 5, lane = tid & 31;
    int gid = lane >> 2, tig = lane & 3;
    int kh = warp >> 1;                 // k16 chunk 0..3
    int wn = (warp & 1) * 32;
    int po = kh * 8;                    // pair offset

    __shared__ __align__(16) uint32_t AsH[2][32 * AST];
    __shared__ __align__(16) uint32_t AsL[2][32 * AST];
    __shared__ __align__(16) uint32_t WsH[2][32 * 64];
    __shared__ __align__(16) uint32_t WsL[2][32 * 64];
    __shared__ float Red[2][32 * 66];

    int a_row = tid >> 3;               // 0..31
    int a_p = (tid & 7) * 4;            // pair 0..28
    int w_p = tid >> 4;                 // 0..15 (pair rows w_p, w_p+16)
    int w_n = (tid & 15) * 4;
    int w_sw = w_n ^ ((w_p & 3) * 8);

    const uint32_t* AbH = g_iselH + (size_t)mBase * (VDIM / 2);
    const uint32_t* AbL = g_iselL + (size_t)mBase * (VDIM / 2);

    uint4 rAh, rAl, rWh[2], rWl[2];
    rAh = *(const uint4*)&AbH[(size_t)a_row * (VDIM / 2) + a_p];
    rAl = *(const uint4*)&AbL[(size_t)a_row * (VDIM / 2) + a_p];
    #pragma unroll
    for (int i = 0; i < 2; i++) {
        size_t off = (size_t)(w_p + i * 16) * HDIM + nBase + w_n;
        rWh[i] = *(const uint4*)&g_WvsH[off];
        rWl[i] = *(const uint4*)&g_WvsL[off];
    }
    *(uint4*)&AsH[0][a_row * AST + a_p] = rAh;
    *(uint4*)&AsL[0][a_row * AST + a_p] = rAl;
    #pragma unroll
    for (int i = 0; i < 2; i++) {
        int off = (w_p + i * 16) * 64 + w_sw;
        *(uint4*)&WsH[0][off] = rWh[i];
        *(uint4*)&WsL[0][off] = rWl[i];
    }
    __syncthreads();

    float acc[2][4][4];
    #pragma unroll
    for (int mi = 0; mi < 2; mi++)
        #pragma unroll
        for (int j = 0; j < 4; j++)
            #pragma unroll
            for (int r = 0; r < 4; r++) acc[mi][j][r] = 0.f;

    for (int t = 0; t < G1_NT; t++) {
        int cur = t & 1;
        if (t + 1 < G1_NT) {
            int p0n = (t + 1) * 32;
            rAh = *(const uint4*)&AbH[(size_t)a_row * (VDIM / 2) + p0n + a_p];
            rAl = *(const uint4*)&AbL[(size_t)a_row * (VDIM / 2) + p0n + a_p];
            #pragma unroll
            for (int i = 0; i < 2; i++) {
                size_t off = (size_t)(p0n + w_p + i * 16) * HDIM + nBase + w_n;
                rWh[i] = *(const uint4*)&g_WvsH[off];
                rWl[i] = *(const uint4*)&g_WvsL[off];
            }
        }
        uint32_t ah[2][4], al[2][4];
        #pragma unroll
        for (int mi = 0; mi < 2; mi++) {
            int r0 = (mi * 16 + gid) * AST + po + tig;
            ah[mi][0] = AsH[cur][r0];
            ah[mi][1] = AsH[cur][r0 + 8 * AST];
            ah[mi][2] = AsH[cur][r0 + 4];
            ah[mi][3] = AsH[cur][r0 + 8 * AST + 4];
            al[mi][0] = AsL[cur][r0];
            al[mi][1] = AsL[cur][r0 + 8 * AST];
            al[mi][2] = AsL[cur][r0 + 4];
            al[mi][3] = AsL[cur][r0 + 8 * AST + 4];
        }
        #pragma unroll
        for (int j = 0; j < 4; j++) {
            int sw = (wn + j * 8 + gid) ^ (tig * 8);
            uint32_t bh[2], bl[2];
            bh[0] = WsH[cur][(po + tig) * 64 + sw];
            bh[1] = WsH[cur][(po + tig + 4) * 64 + sw];
            bl[0] = WsL[cur][(po + tig) * 64 + sw];
            bl[1] = WsL[cur][(po + tig + 4) * 64 + sw];
            mma16(acc[0][j], ah[0], bh);
            mma16(acc[0][j], ah[0], bl);
            mma16(acc[0][j], al[0], bh);
            mma16(acc[1][j], ah[1], bh);
            mma16(acc[1][j], ah[1], bl);
            mma16(acc[1][j], al[1], bh);
        }
        if (t + 1 < G1_NT) {
            int nx = cur ^ 1;
            *(uint4*)&AsH[nx][a_row * AST + a_p] = rAh;
            *(uint4*)&AsL[nx][a_row * AST + a_p] = rAl;
            #pragma unroll
            for (int i = 0; i < 2; i++) {
                int off = (w_p + i * 16) * 64 + w_sw;
                *(uint4*)&WsH[nx][off] = rWh[i];
                *(uint4*)&WsL[nx][off] = rWl[i];
            }
        }
        __syncthreads();
    }

    if (kh >= 2) {
        float* R = Red[kh - 2];
        #pragma unroll
        for (int mi = 0; mi < 2; mi++) {
            int r0 = mi * 16 + gid;
            #pragma unroll
            for (int j = 0; j < 4; j++) {
                int col = wn + j * 8 + 2 * tig;
                R[r0 * 66 + col] = acc[mi][j][0];
                R[r0 * 66 + col + 1] = acc[mi][j][1];
                R[(r0 + 8) * 66 + col] = acc[mi][j][2];
                R[(r0 + 8) * 66 + col + 1] = acc[mi][j][3];
            }
        }
    }
    __syncthreads();
    if (kh < 2) {
        const float* R = Red[kh];
        #pragma unroll
        for (int mi = 0; mi < 2; mi++) {
            int r0 = mi * 16 + gid;
            #pragma unroll
            for (int j = 0; j < 4; j++) {
                int col = wn + j * 8 + 2 * tig;
                acc[mi][j][0] += R[r0 * 66 + col];
                acc[mi][j][1] += R[r0 * 66 + col + 1];
                acc[mi][j][2] += R[(r0 + 8) * 66 + col];
                acc[mi][j][3] += R[(r0 + 8) * 66 + col + 1];
            }
        }
    }
    __syncthreads();
    if (kh == 1) {
        float* R = Red[0];
        #pragma unroll
        for (int mi = 0; mi < 2; mi++) {
            int r0 = mi * 16 + gid;
            #pragma unroll
            for (int j = 0; j < 4; j++) {
                int col = wn + j * 8 + 2 * tig;
                R[r0 * 66 + col] = acc[mi][j][0];
                R[r0 * 66 + col + 1] = acc[mi][j][1];
                R[(r0 + 8) * 66 + col] = acc[mi][j][2];
                R[(r0 + 8) * 66 + col + 1] = acc[mi][j][3];
            }
        }
    }
    __syncthreads();
    if (kh == 0) {
        const float* R = Red[0];
        #pragma unroll
        for (int mi = 0; mi < 2; mi++) {
            int r0 = mi * 16 + gid;
            #pragma unroll
            for (int j = 0; j < 4; j++) {
                int col = wn + j * 8 + 2 * tig;
                int cg = nBase + col;
                float b0 = bias[cg], b1 = bias[cg + 1];
                float2 o0, o1;
                o0.x = acc[mi][j][0] + R[r0 * 66 + col] + b0;
                o0.y = acc[mi][j][1] + R[r0 * 66 + col + 1] + b1;
                o1.x = acc[mi][j][2] + R[(r0 + 8) * 66 + col] + b0;
                o1.y = acc[mi][j][3] + R[(r0 + 8) * 66 + col + 1] + b1;
                *(float2*)&g_vis[(size_t)(mBase + r0) * HDIM + cg] = o0;
                *(float2*)&g_vis[(size_t)(mBase + r0 + 8) * HDIM + cg] = o1;
            }
        }
    }
}

// ---------------- K4: FUSED gates + gate-scale + pack-split --------------
// Block handles 4 rows: 2 warps/row compute logits; then all 256 threads
// scale+split those rows into the concat activation planes.
__global__ __launch_bounds__(256) void gate_kernel(const float* __restrict__ tag,
                                                   const float* __restrict__ pos,
                                                   const float* __restrict__ Wsoft,
                                                   const float* __restrict__ bsoft) {
    int tid = threadIdx.x;
    int w = tid >> 5, lane = tid & 31;
    int rb = blockIdx.x * 4;
    int r = rb + (w >> 1);
    int half = w & 1;
    __shared__ float pl[8][2];
    __shared__ float w0s[4], w1s[4];

    {
        const float4* v = (const float4*)(g_vis + (size_t)r * HDIM);
        const float4* t = (const float4*)(tag + (size_t)r * HDIM);
        const float4* p = (const float4*)(pos + (size_t)r * HDIM);
        const float4* Wq = (const float4*)Wsoft;
        float l0 = 0.f, l1 = 0.f;
        #pragma unroll
        for (int i = 0; i < 2; i++) {
            int h4 = half * 64 + i * 32 + lane;
            float4 a = v[h4], c = t[h4], e = p[h4];
            float s0 = a.x + c.x + e.x, s1 = a.y + c.y + e.y;
            float s2 = a.z + c.z + e.z, s3 = a.w + c.w + e.w;
            float4 w01 = Wq[h4 * 2], w23 = Wq[h4 * 2 + 1];
            l0 += s0 * w01.x + s1 * w01.z + s2 * w23.x + s3 * w23.z;
            l1 += s0 * w01.y + s1 * w01.w + s2 * w23.y + s3 * w23.w;
        }
        #pragma unroll
        for (int o = 16; o; o >>= 1) {
            l0 += __shfl_xor_sync(0xffffffffu, l0, o);
            l1 += __shfl_xor_sync(0xffffffffu, l1, o);
        }
        if (lane == 0) { pl[w][0] = l0; pl[w][1] = l1; }
    }
    __syncthreads();
    if (tid < 4) {
        float L0 = pl[tid * 2][0] + pl[tid * 2 + 1][0];
        float L1 = pl[tid * 2][1] + pl[tid * 2 + 1][1];
        L0 = (L0 + bsoft[0]) / 0.03f;
        L1 = (L1 + bsoft[1]) / 0.03f;
        float m = fmaxf(L0, L1);
        float lse = m + logf(expf(L0 - m) + expf(L1 - m));
        w0s[tid] = L0 - lse;
        w1s[tid] = L1 - lse;
    }
    __syncthreads();

    // scale + split: thread -> (row rl = tid>>6, chunk c = tid&63 of 8 floats)
    int rl = tid >> 6;
    int c = tid & 63;
    int row = rb + rl;
    float w0 = w0s[rl], w1 = w1s[rl];
    const float* v = g_vis + (size_t)row * HDIM + c * 8;
    const float* t = tag + (size_t)row * HDIM + c * 8;
    float4 v0 = *(const float4*)v, v1 = *(const float4*)(v + 4);
    float4 t0 = *(const float4*)t, t1 = *(const float4*)(t + 4);
    v0.x *= w0; v0.y *= w0; v0.z *= w0; v0.w *= w0;
    v1.x *= w0; v1.y *= w0; v1.z *= w0; v1.w *= w0;
    t0.x *= w1; t0.y *= w1; t0.z *= w1; t0.w *= w1;
    t1.x *= w1; t1.y *= w1; t1.z *= w1; t1.w *= w1;
    uint4 h, l;
    split_pair(v0.x, v0.y, h.x, l.x);
    split_pair(v0.z, v0.w, h.y, l.y);
    split_pair(v1.x, v1.y, h.z, l.z);
    split_pair(v1.z, v1.w, h.w, l.w);
    *(uint4*)&g_XYH[(size_t)row * HDIM + c * 4] = h;
    *(uint4*)&g_XYL[(size_t)row * HDIM + c * 4] = l;
    split_pair(t0.x, t0.y, h.x, l.x);
    split_pair(t0.z, t0.w, h.y, l.y);
    split_pair(t1.x, t1.y, h.z, l.z);
    split_pair(t1.z, t1.w, h.w, l.w);
    *(uint4*)&g_XYH[(size_t)row * HDIM + 256 + c * 4] = h;
    *(uint4*)&g_XYL[(size_t)row * HDIM + 256 + c * 4] = l;
}

// ---------------- K5: vis2 concat-K GEMM (3x bf16) -----------------------
#define G2_NT ((2 * HDIM) / 64)
__global__ __launch_bounds__(256) void gemm2_kernel(
    const float* __restrict__ bvp, const float* __restrict__ btg,
    const float* __restrict__ pos) {
    int mBase = blockIdx.y * 32;
    int nBase = blockIdx.x * 64;
    int tid = threadIdx.x;
    int warp = tid >> 5, lane = tid & 31;
    int gid = lane >> 2, tig = lane & 3;
    int kh = warp >> 1;
    int wn = (warp & 1) * 32;
    int po = kh * 8;

    __shared__ __align__(16) uint32_t AsH[2][32 * AST];
    __shared__ __align__(16) uint32_t AsL[2][32 * AST];
    __shared__ __align__(16) uint32_t WsH[2][32 * 64];
    __shared__ __align__(16) uint32_t WsL[2][32 * 64];
    __shared__ float Red[2][32 * 66];

    int a_row = tid >> 3;
    int a_p = (tid & 7) * 4;
    int w_p = tid >> 4;
    int w_n = (tid & 15) * 4;
    int w_sw = w_n ^ ((w_p & 3) * 8);

    const uint32_t* AbH = g_XYH + (size_t)mBase * HDIM;
    const uint32_t* AbL = g_XYL + (size_t)mBase * HDIM;

    uint4 rAh, rAl, rWh[2], rWl[2];
    rAh = *(const uint4*)&AbH[(size_t)a_row * HDIM + a_p];
    rAl = *(const uint4*)&AbL[(size_t)a_row * HDIM + a_p];
    #pragma unroll
    for (int i = 0; i < 2; i++) {
        size_t off = (size_t)(w_p + i * 16) * HDIM + nBase + w_n;
        rWh[i] = *(const uint4*)&g_WcH[off];
        rWl[i] = *(const uint4*)&g_WcL[off];
    }
    *(uint4*)&AsH[0][a_row * AST + a_p] = rAh;
    *(uint4*)&AsL[0][a_row * AST + a_p] = rAl;
    #pragma unroll
    for (int i = 0; i < 2; i++) {
        int off = (w_p + i * 16) * 64 + w_sw;
        *(uint4*)&WsH[0][off] = rWh[i];
        *(uint4*)&WsL[0][off] = rWl[i];
    }
    __syncthreads();

    float acc[2][4][4];
    #pragma unroll
    for (int mi = 0; mi < 2; mi++)
        #pragma unroll
        for (int j = 0; j < 4; j++)
            #pragma unroll
            for (int r = 0; r < 4; r++) acc[mi][j][r] = 0.f;

    for (int t = 0; t < G2_NT; t++) {
        int cur = t & 1;
        if (t + 1 < G2_NT) {
            int p0n = (t + 1) * 32;
            rAh = *(const uint4*)&AbH[(size_t)a_row * HDIM + p0n + a_p];
            rAl = *(const uint4*)&AbL[(size_t)a_row * HDIM + p0n + a_p];
            #pragma unroll
            for (int i = 0; i < 2; i++) {
                size_t off = (size_t)(p0n + w_p + i * 16) * HDIM + nBase + w_n;
                rWh[i] = *(const uint4*)&g_WcH[off];
                rWl[i] = *(const uint4*)&g_WcL[off];
            }
        }
        uint32_t ah[2][4], al[2][4];
        #pragma unroll
        for (int mi = 0; mi < 2; mi++) {
            int r0 = (mi * 16 + gid) * AST + po + tig;
            ah[mi][0] = AsH[cur][r0];
            ah[mi][1] = AsH[cur][r0 + 8 * AST];
            ah[mi][2] = AsH[cur][r0 + 4];
            ah[mi][3] = AsH[cur][r0 + 8 * AST + 4];
            al[mi][0] = AsL[cur][r0];
            al[mi][1] = AsL[cur][r0 + 8 * AST];
            al[mi][2] = AsL[cur][r0 + 4];
            al[mi][3] = AsL[cur][r0 + 8 * AST + 4];
        }
        #pragma unroll
        for (int j = 0; j < 4; j++) {
            int sw = (wn + j * 8 + gid) ^ (tig * 8);
            uint32_t bh[2], bl[2];
            bh[0] = WsH[cur][(po + tig) * 64 + sw];
            bh[1] = WsH[cur][(po + tig + 4) * 64 + sw];
            bl[0] = WsL[cur][(po + tig) * 64 + sw];
            bl[1] = WsL[cur][(po + tig + 4) * 64 + sw];
            mma16(acc[0][j], ah[0], bh);
            mma16(acc[0][j], ah[0], bl);
            mma16(acc[0][j], al[0], bh);
            mma16(acc[1][j], ah[1], bh);
            mma16(acc[1][j], ah[1], bl);
            mma16(acc[1][j], al[1], bh);
        }
        if (t + 1 < G2_NT) {
            int nx = cur ^ 1;
            *(uint4*)&AsH[nx][a_row * AST + a_p] = rAh;
            *(uint4*)&AsL[nx][a_row * AST + a_p] = rAl;
            #pragma unroll
            for (int i = 0; i < 2; i++) {
                int off = (w_p + i * 16) * 64 + w_sw;
                *(uint4*)&WsH[nx][off] = rWh[i];
                *(uint4*)&WsL[nx][off] = rWl[i];
            }
        }
        __syncthreads();
    }

    if (kh >= 2) {
        float* R = Red[kh - 2];
        #pragma unroll
        for (int mi = 0; mi < 2; mi++) {
            int r0 = mi * 16 + gid;
            #pragma unroll
            for (int j = 0; j < 4; j++) {
                int col = wn + j * 8 + 2 * tig;
                R[r0 * 66 + col] = acc[mi][j][0];
                R[r0 * 66 + col + 1] = acc[mi][j][1];
                R[(r0 + 8) * 66 + col] = acc[mi][j][2];
                R[(r0 + 8) * 66 + col + 1] = acc[mi][j][3];
            }
        }
    }
    __syncthreads();
    if (kh < 2) {
        const float* R = Red[kh];
        #pragma unroll
        for (int mi = 0; mi < 2; mi++) {
            int r0 = mi * 16 + gid;
            #pragma unroll
            for (int j = 0; j < 4; j++) {
                int col = wn + j * 8 + 2 * tig;
                acc[mi][j][0] += R[r0 * 66 + col];
                acc[mi][j][1] += R[r0 * 66 + col + 1];
                acc[mi][j][2] += R[(r0 + 8) * 66 + col];
                acc[mi][j][3] += R[(r0 + 8) * 66 + col + 1];
            }
        }
    }
    __syncthreads();
    if (kh == 1) {
        float* R = Red[0];
        #pragma unroll
        for (int mi = 0; mi < 2; mi++) {
            int r0 = mi * 16 + gid;
            #pragma unroll
            for (int j = 0; j < 4; j++) {
                int col = wn + j * 8 + 2 * tig;
                R[r0 * 66 + col] = acc[mi][j][0];
                R[r0 * 66 + col + 1] = acc[mi][j][1];
                R[(r0 + 8) * 66 + col] = acc[mi][j][2];
                R[(r0 + 8) * 66 + col + 1] = acc[mi][j][3];
            }
        }
    }
    __syncthreads();
    if (kh == 0) {
        const float* R = Red[0];
        #pragma unroll
        for (int mi = 0; mi < 2; mi++) {
            int r0 = mi * 16 + gid;
            #pragma unroll
            for (int j = 0; j < 4; j++) {
                int col = wn + j * 8 + 2 * tig;
                int cg = nBase + col;
                float b0 = bvp[cg] + btg[cg];
                float b1 = bvp[cg + 1] + btg[cg + 1];
                size_t ro0 = (size_t)(mBase + r0) * HDIM + cg;
                size_t ro1 = (size_t)(mBase + r0 + 8) * HDIM + cg;
                float2 p0 = *(const float2*)&pos[ro0];
                float2 p1 = *(const float2*)&pos[ro1];
                float2 o0, o1;
                o0.x = acc[mi][j][0] + R[r0 * 66 + col] + b0 + p0.x;
                o0.y = acc[mi][j][1] + R[r0 * 66 + col + 1] + b1 + p0.y;
                o1.x = acc[mi][j][2] + R[(r0 + 8) * 66 + col] + b0 + p1.x;
                o1.y = acc[mi][j][3] + R[(r0 + 8) * 66 + col + 1] + b1 + p1.y;
                *(float2*)&g_vis2[ro0] = o0;
                *(float2*)&g_vis2[ro1] = o1;
            }
        }
    }
}

// ---------------- K6: cosine sim + argmax + box decode (lang precomputed) -
__global__ __launch_bounds__(1024) void final_kernel(
    const float* __restrict__ boxes, float* __restrict__ out) {
    int b = blockIdx.x, tid = threadIdx.x;   // 1024 threads = 32 warps
    int w = tid >> 5, lane = tid & 31;
    __shared__ float le[HDIM];
    __shared__ float ssim[SEL];

    if (tid < HDIM) le[tid] = g_lang[b * HDIM + tid];
    __syncthreads();

    const float4* v2 = (const float4*)(g_vis2 + (size_t)(b * SEL + w) * HDIM);
    const float4* lef = (const float4*)le;
    float d = 0.f, q = 0.f;
    #pragma unroll
    for (int i = 0; i < 4; i++) {
        float4 a = v2[lane + i * 32];
        float4 c = lef[lane + i * 32];
        d += a.x * c.x + a.y * c.y + a.z * c.z + a.w * c.w;
        q += a.x * a.x + a.y * a.y + a.z * a.z + a.w * a.w;
    }
    #pragma unroll
    for (int o = 16; o; o >>= 1) {
        d += __shfl_xor_sync(0xffffffffu, d, o);
        q += __shfl_xor_sync(0xffffffffu, q, o);
    }
    if (lane == 0) ssim[w] = d / ((sqrtf(q) + EPSF) * g_ln[b]);
    __syncthreads();

    if (tid < SEL) out[BS * 5 + b * SEL + tid] = ssim[tid];

    if (w == 0) {
        float v = ssim[lane]; int bi = lane;
        #pragma unroll
        for (int o = 16; o; o >>= 1) {
            float ov = __shfl_down_sync(0xffffffffu, v, o);
            int   oi = __shfl_down_sync(0xffffffffu, bi, o);
            if (ov > v || (ov == v && oi < bi)) { v = ov; bi = oi; }
        }
        if (lane == 0) {
            int g = g_idx[b * SEL + bi];
            const float* base = boxes + ((size_t)b * GRID_N + g) * A_N * CH;
            int j = 0; float ov = base[4];
            for (int a = 1; a < A_N; a++) {
                float o2 = base[a * CH + 4];
                if (o2 > ov) { ov = o2; j = a; }
            }
            float x = base[j * CH + 0], y = base[j * CH + 1];
            float wd = base[j * CH + 2], hh = base[j * CH + 3];
            float x1 = x - wd * 0.5f, y1 = y - hh * 0.5f;
            out[b * 5 + 0] = x1;
            out[b * 5 + 1] = y1;
            out[b * 5 + 2] = x1 + wd;
            out[b * 5 + 3] = y1 + hh;
            out[b * 5 + 4] = ov;
        }
    }
}

// ---------------- launch --------------------------------------------------
extern "C" void kernel_launch(void* const* d_in, const int* in_sizes, int n_in,
                              void* d_out, int out_size) {
    const float* boxes    = (const float*)d_in[0];
    const float* x_feat   = (const float*)d_in[1];
    const float* tag_emb  = (const float*)d_in[2];
    const float* pos_emb  = (const float*)d_in[3];
    const float* lang     = (const float*)d_in[4];
    const float* W_vs     = (const float*)d_in[5];
    const float* b_vs     = (const float*)d_in[6];
    const float* W_ts     = (const float*)d_in[7];
    const float* b_ts     = (const float*)d_in[8];
    const float* W_vs_pos = (const float*)d_in[9];
    const float* b_vs_pos = (const float*)d_in[10];
    const float* W_tag    = (const float*)d_in[11];
    const float* b_tag    = (const float*)d_in[12];
    const float* W_soft   = (const float*)d_in[13];
    const float* b_soft   = (const float*)d_in[14];
    float* out = (float*)d_out;

    wsplit_kernel<<<544, 256>>>(W_vs, W_vs_pos, W_tag, lang, W_ts, b_ts);
    topk_kernel<<<BS, 256>>>(boxes);
    gather_kernel<<<BS * SEL, 256>>>(x_feat);
    gemm1_kernel<<<dim3(HDIM / 64, ROWS / 32), 256>>>(b_vs);
    gate_kernel<<<ROWS / 4, 256>>>(tag_emb, pos_emb, W_soft, b_soft);
    gemm2_kernel<<<dim3(HDIM / 64, ROWS / 32), 256>>>(b_vs_pos, b_tag, pos_emb);
    final_kernel<<<BS, 1024>>>(boxes, out);
}

// round 17
// speedup vs baseline: 1.2927x; 1.2927x over previous
#include <cuda_runtime.h>
#include <math.h>
#include <stdint.h>

#define BS     32
#define GRID_N 2704
#define A_N    3
#define CH     85
#define VDIM   1024
#define HDIM   512
#define SEL    32
#define ROWS   (BS * SEL)          // 1024 flattened rows
#define EPSF   1e-8f

// ---------------- device scratch (static, no allocation) ----------------
__device__ int      g_idx[BS * SEL];
__device__ uint32_t g_iselH[(size_t)ROWS * (VDIM / 2)];   // packed bf16 hi pairs
__device__ uint32_t g_iselL[(size_t)ROWS * (VDIM / 2)];   // packed bf16 lo pairs
__device__ float    g_vis[(size_t)ROWS * HDIM];
__device__ float    g_vis2[(size_t)ROWS * HDIM];
// presplit weights (packed bf16 pairs along K)
__device__ uint32_t g_WvsH[(size_t)(VDIM / 2) * HDIM];
__device__ uint32_t g_WvsL[(size_t)(VDIM / 2) * HDIM];
__device__ uint32_t g_WcH[(size_t)HDIM * HDIM];           // [Wvp ; Wtg] concat pairs
__device__ uint32_t g_WcL[(size_t)HDIM * HDIM];
// presplit gated activations for gemm2: [vis*w0 | tag*w1] concat pairs
__device__ uint32_t g_XYH[(size_t)ROWS * HDIM];
__device__ uint32_t g_XYL[(size_t)ROWS * HDIM];

// ---------------- bf16 split helpers --------------------------------------
__device__ __forceinline__ uint32_t pack_bf16x2(float lo, float hi) {
    uint32_t r;
    asm("cvt.rn.bf16x2.f32 %0, %1, %2;" : "=r"(r) : "f"(hi), "f"(lo));
    return r;
}
__device__ __forceinline__ void split_pair(float x0, float x1, uint32_t& hp, uint32_t& lp) {
    hp = pack_bf16x2(x0, x1);
    float h0 = __uint_as_float(hp << 16);
    float h1 = __uint_as_float(hp & 0xFFFF0000u);
    lp = pack_bf16x2(x0 - h0, x1 - h1);
}
__device__ __forceinline__ void mma16(float d[4], const uint32_t a[4], const uint32_t b[2]) {
    asm volatile(
        "mma.sync.aligned.m16n8k16.row.col.f32.bf16.bf16.f32 "
        "{%0,%1,%2,%3}, {%4,%5,%6,%7}, {%8,%9}, {%0,%1,%2,%3};"
        : "+f"(d[0]), "+f"(d[1]), "+f"(d[2]), "+f"(d[3])
        : "r"(a[0]), "r"(a[1]), "r"(a[2]), "r"(a[3]), "r"(b[0]), "r"(b[1]));
}

// ---------------- K0: presplit weights into packed bf16 pair planes ------
__global__ __launch_bounds__(256) void wsplit_kernel(const float* __restrict__ Wvs,
                                                     const float* __restrict__ Wvp,
                                                     const float* __restrict__ Wtg) {
    int i = blockIdx.x * 256 + threadIdx.x;   // 0 .. 131071
    if (i < 65536) {
        int p = i >> 7;                       // pair row 0..511 (VDIM/2)
        int n4 = (i & 127) * 4;
        float4 r0 = *(const float4*)&Wvs[(size_t)(2 * p) * HDIM + n4];
        float4 r1 = *(const float4*)&Wvs[(size_t)(2 * p + 1) * HDIM + n4];
        uint4 h, l;
        split_pair(r0.x, r1.x, h.x, l.x);
        split_pair(r0.y, r1.y, h.y, l.y);
        split_pair(r0.z, r1.z, h.z, l.z);
        split_pair(r0.w, r1.w, h.w, l.w);
        *(uint4*)&g_WvsH[(size_t)p * HDIM + n4] = h;
        *(uint4*)&g_WvsL[(size_t)p * HDIM + n4] = l;
    } else {
        int j = i - 65536;
        int p = j >> 7;                       // concat pair row 0..511
        int n4 = (j & 127) * 4;
        const float* W = (p < 256) ? Wvp : Wtg;
        int pp = (p < 256) ? p : p - 256;
        float4 r0 = *(const float4*)&W[(size_t)(2 * pp) * HDIM + n4];
        float4 r1 = *(const float4*)&W[(size_t)(2 * pp + 1) * HDIM + n4];
        uint4 h, l;
        split_pair(r0.x, r1.x, h.x, l.x);
        split_pair(r0.y, r1.y, h.y, l.y);
        split_pair(r0.z, r1.z, h.z, l.z);
        split_pair(r0.w, r1.w, h.w, l.w);
        *(uint4*)&g_WcH[(size_t)p * HDIM + n4] = h;
        *(uint4*)&g_WcL[(size_t)p * HDIM + n4] = l;
    }
}

// ---------------- K1: objectness score + exact top-32 via histogram ------
__global__ void topk_kernel(const float* __restrict__ boxes) {
    int b = blockIdx.x;
    int tid = threadIdx.x;          // 256 threads
    __shared__ float sc[GRID_N];
    __shared__ int   hist[512];
    __shared__ int   s_binB, s_definite;
    __shared__ int   cnt_hi, cnt_cb, overflow;
    __shared__ int   hi_idx[SEL];
    __shared__ float cb_sc[512];
    __shared__ int   cb_idx[512];
    __shared__ int   sel[SEL];
    __shared__ float rv[8];
    __shared__ int   ri[8];

    for (int i = tid; i < 512; i += 256) hist[i] = 0;
    if (tid == 0) { cnt_hi = 0; cnt_cb = 0; overflow = 0; }
    __syncthreads();

    const float* bb = boxes + (size_t)b * GRID_N * A_N * CH;
    for (int g = tid; g < GRID_N; g += 256) {
        const float* p = bb + (size_t)g * A_N * CH;
        float s = (p[4] + p[CH + 4] + p[2 * CH + 4]) * (1.0f / 3.0f);
        sc[g] = s;
        int bin = (int)(s * 512.0f);
        bin = max(0, min(511, bin));
        atomicAdd(&hist[bin], 1);
    }
    __syncthreads();

    if (tid == 0) {
        int cum = 0, bB = 0, def = 0;
        for (int v = 511; v >= 0; v--) {
            cum += hist[v];
            if (cum >= SEL) { bB = v; def = cum - hist[v]; break; }
        }
        s_binB = bB; s_definite = def;
    }
    __syncthreads();
    int binB = s_binB;

    for (int g = tid; g < GRID_N; g += 256) {
        float s = sc[g];
        int bin = (int)(s * 512.0f);
        bin = max(0, min(511, bin));
        if (bin > binB) {
            int p = atomicAdd(&cnt_hi, 1);
            hi_idx[p] = g;
        } else if (bin == binB) {
            int p = atomicAdd(&cnt_cb, 1);
            if (p < 512) { cb_sc[p] = s; cb_idx[p] = g; }
            else overflow = 1;
        }
    }
    __syncthreads();

    if (!overflow) {
        if (tid >= 32 && (tid - 32) < s_definite) sel[tid - 32] = hi_idx[tid - 32];
        if (tid < 32) {
            int need = SEL - s_definite;
            int n = min(cnt_cb, 512);
            for (int it = 0; it < need; it++) {
                float best = -1e30f; int bi = GRID_N;
                for (int c = tid; c < n; c += 32) {
                    float v = cb_sc[c]; int gi = cb_idx[c];
                    if (v > best || (v == best && gi < bi)) { best = v; bi = gi; }
                }
                #pragma unroll
                for (int o = 16; o; o >>= 1) {
                    float ov = __shfl_down_sync(0xffffffffu, best, o);
                    int   oi = __shfl_down_sync(0xffffffffu, bi, o);
                    if (ov > best || (ov == best && oi < bi)) { best = ov; bi = oi; }
                }
                bi = __shfl_sync(0xffffffffu, bi, 0);
                if (tid == 0) sel[s_definite + it] = bi;
                for (int c = tid; c < n; c += 32)
                    if (cb_idx[c] == bi) cb_sc[c] = -1e30f;
                __syncwarp();
            }
        }
    }
    __syncthreads();

    if (overflow) {
        for (int it = 0; it < SEL; it++) {
            float best = -1e30f;
            int   bi = GRID_N;
            for (int g = tid; g < GRID_N; g += 256) {
                float v = sc[g];
                if (v > best) { best = v; bi = g; }
            }
            #pragma unroll
            for (int o = 16; o; o >>= 1) {
                float ov = __shfl_down_sync(0xffffffffu, best, o);
                int   oi = __shfl_down_sync(0xffffffffu, bi, o);
                if (ov > best || (ov == best && oi < bi)) { best = ov; bi = oi; }
            }
            if ((tid & 31) == 0) { rv[tid >> 5] = best; ri[tid >> 5] = bi; }
            __syncthreads();
            if (tid == 0) {
                float B = rv[0]; int BI = ri[0];
                for (int w = 1; w < 8; w++)
                    if (rv[w] > B || (rv[w] == B && ri[w] < BI)) { B = rv[w]; BI = ri[w]; }
                sel[it] = BI;
                sc[BI] = -1e30f;
            }
            __syncthreads();
        }
    }

    if (tid == 0) {
        for (int i = 1; i < SEL; i++) {
            int v = sel[i], j = i - 1;
            while (j >= 0 && sel[j] > v) { sel[j + 1] = sel[j]; j--; }
            sel[j + 1] = v;
        }
        for (int i = 0; i < SEL; i++) g_idx[b * SEL + i] = sel[i];
    }
}

// ---------------- K2: gather + pack-split selected feature columns -------
__global__ void gather_kernel(const float* __restrict__ xfeat) {
    int row = blockIdx.x;           // b*SEL + s
    int b = row >> 5;
    int g = g_idx[row];
    const float* src = xfeat + (size_t)b * VDIM * GRID_N + g;
    uint32_t* dh = g_iselH + (size_t)row * (VDIM / 2);
    uint32_t* dl = g_iselL + (size_t)row * (VDIM / 2);
    for (int p = threadIdx.x; p < VDIM / 2; p += blockDim.x) {
        float x0 = __ldg(&src[(size_t)(2 * p) * GRID_N]);
        float x1 = __ldg(&src[(size_t)(2 * p + 1) * GRID_N]);
        uint32_t hp, lp;
        split_pair(x0, x1, hp, lp);
        dh[p] = hp;
        dl[p] = lp;
    }
}

// ============ GEMM skeleton: block 32(M)x64(N), BK=64 (32 pairs), 8 warps =
#define AST 36

// ---------------- K3: vis = isel @ W_vs + b_vs (3x bf16) -----------------
#define G1_NT (VDIM / 64)
__global__ __launch_bounds__(256) void gemm1_kernel(const float* __restrict__ bias) {
    int mBase = blockIdx.y * 32;
    int nBase = blockIdx.x * 64;
    int tid = threadIdx.x;
    int warp = tid >> 5, lane = tid & 31;
    int gid = lane >> 2, tig = lane & 3;
    int kh = warp >> 1;                 // k16 chunk 0..3
    int wn = (warp & 1) * 32;
    int po = kh * 8;                    // pair offset

    __shared__ __align__(16) uint32_t AsH[2][32 * AST];
    __shared__ __align__(16) uint32_t AsL[2][32 * AST];
    __shared__ __align__(16) uint32_t WsH[2][32 * 64];
    __shared__ __align__(16) uint32_t WsL[2][32 * 64];
    __shared__ float Red[2][32 * 66];

    int a_row = tid >> 3;               // 0..31
    int a_p = (tid & 7) * 4;            // pair 0..28
    int w_p = tid >> 4;                 // 0..15 (pair rows w_p, w_p+16)
    int w_n = (tid & 15) * 4;
    int w_sw = w_n ^ ((w_p & 3) * 8);

    const uint32_t* AbH = g_iselH + (size_t)mBase * (VDIM / 2);
    const uint32_t* AbL = g_iselL + (size_t)mBase * (VDIM / 2);

    uint4 rAh, rAl, rWh[2], rWl[2];
    rAh = *(const uint4*)&AbH[(size_t)a_row * (VDIM / 2) + a_p];
    rAl = *(const uint4*)&AbL[(size_t)a_row * (VDIM / 2) + a_p];
    #pragma unroll
    for (int i = 0; i < 2; i++) {
        size_t off = (size_t)(w_p + i * 16) * HDIM + nBase + w_n;
        rWh[i] = *(const uint4*)&g_WvsH[off];
        rWl[i] = *(const uint4*)&g_WvsL[off];
    }
    *(uint4*)&AsH[0][a_row * AST + a_p] = rAh;
    *(uint4*)&AsL[0][a_row * AST + a_p] = rAl;
    #pragma unroll
    for (int i = 0; i < 2; i++) {
        int off = (w_p + i * 16) * 64 + w_sw;
        *(uint4*)&WsH[0][off] = rWh[i];
        *(uint4*)&WsL[0][off] = rWl[i];
    }
    __syncthreads();

    float acc[2][4][4];
    #pragma unroll
    for (int mi = 0; mi < 2; mi++)
        #pragma unroll
        for (int j = 0; j < 4; j++)
            #pragma unroll
            for (int r = 0; r < 4; r++) acc[mi][j][r] = 0.f;

    for (int t = 0; t < G1_NT; t++) {
        int cur = t & 1;
        if (t + 1 < G1_NT) {
            int p0n = (t + 1) * 32;
            rAh = *(const uint4*)&AbH[(size_t)a_row * (VDIM / 2) + p0n + a_p];
            rAl = *(const uint4*)&AbL[(size_t)a_row * (VDIM / 2) + p0n + a_p];
            #pragma unroll
            for (int i = 0; i < 2; i++) {
                size_t off = (size_t)(p0n + w_p + i * 16) * HDIM + nBase + w_n;
                rWh[i] = *(const uint4*)&g_WvsH[off];
                rWl[i] = *(const uint4*)&g_WvsL[off];
            }
        }
        uint32_t ah[2][4], al[2][4];
        #pragma unroll
        for (int mi = 0; mi < 2; mi++) {
            int r0 = (mi * 16 + gid) * AST + po + tig;
            ah[mi][0] = AsH[cur][r0];
            ah[mi][1] = AsH[cur][r0 + 8 * AST];
            ah[mi][2] = AsH[cur][r0 + 4];
            ah[mi][3] = AsH[cur][r0 + 8 * AST + 4];
            al[mi][0] = AsL[cur][r0];
            al[mi][1] = AsL[cur][r0 + 8 * AST];
            al[mi][2] = AsL[cur][r0 + 4];
            al[mi][3] = AsL[cur][r0 + 8 * AST + 4];
        }
        #pragma unroll
        for (int j = 0; j < 4; j++) {
            int sw = (wn + j * 8 + gid) ^ (tig * 8);
            uint32_t bh[2], bl[2];
            bh[0] = WsH[cur][(po + tig) * 64 + sw];
            bh[1] = WsH[cur][(po + tig + 4) * 64 + sw];
            bl[0] = WsL[cur][(po + tig) * 64 + sw];
            bl[1] = WsL[cur][(po + tig + 4) * 64 + sw];
            mma16(acc[0][j], ah[0], bh);
            mma16(acc[0][j], ah[0], bl);
            mma16(acc[0][j], al[0], bh);
            mma16(acc[1][j], ah[1], bh);
            mma16(acc[1][j], ah[1], bl);
            mma16(acc[1][j], al[1], bh);
        }
        if (t + 1 < G1_NT) {
            int nx = cur ^ 1;
            *(uint4*)&AsH[nx][a_row * AST + a_p] = rAh;
            *(uint4*)&AsL[nx][a_row * AST + a_p] = rAl;
            #pragma unroll
            for (int i = 0; i < 2; i++) {
                int off = (w_p + i * 16) * 64 + w_sw;
                *(uint4*)&WsH[nx][off] = rWh[i];
                *(uint4*)&WsL[nx][off] = rWl[i];
            }
        }
        __syncthreads();
    }

    if (kh >= 2) {
        float* R = Red[kh - 2];
        #pragma unroll
        for (int mi = 0; mi < 2; mi++) {
            int r0 = mi * 16 + gid;
            #pragma unroll
            for (int j = 0; j < 4; j++) {
                int col = wn + j * 8 + 2 * tig;
                R[r0 * 66 + col] = acc[mi][j][0];
                R[r0 * 66 + col + 1] = acc[mi][j][1];
                R[(r0 + 8) * 66 + col] = acc[mi][j][2];
                R[(r0 + 8) * 66 + col + 1] = acc[mi][j][3];
            }
        }
    }
    __syncthreads();
    if (kh < 2) {
        const float* R = Red[kh];
        #pragma unroll
        for (int mi = 0; mi < 2; mi++) {
            int r0 = mi * 16 + gid;
            #pragma unroll
            for (int j = 0; j < 4; j++) {
                int col = wn + j * 8 + 2 * tig;
                acc[mi][j][0] += R[r0 * 66 + col];
                acc[mi][j][1] += R[r0 * 66 + col + 1];
                acc[mi][j][2] += R[(r0 + 8) * 66 + col];
                acc[mi][j][3] += R[(r0 + 8) * 66 + col + 1];
            }
        }
    }
    __syncthreads();
    if (kh == 1) {
        float* R = Red[0];
        #pragma unroll
        for (int mi = 0; mi < 2; mi++) {
            int r0 = mi * 16 + gid;
            #pragma unroll
            for (int j = 0; j < 4; j++) {
                int col = wn + j * 8 + 2 * tig;
                R[r0 * 66 + col] = acc[mi][j][0];
                R[r0 * 66 + col + 1] = acc[mi][j][1];
                R[(r0 + 8) * 66 + col] = acc[mi][j][2];
                R[(r0 + 8) * 66 + col + 1] = acc[mi][j][3];
            }
        }
    }
    __syncthreads();
    if (kh == 0) {
        const float* R = Red[0];
        #pragma unroll
        for (int mi = 0; mi < 2; mi++) {
            int r0 = mi * 16 + gid;
            #pragma unroll
            for (int j = 0; j < 4; j++) {
                int col = wn + j * 8 + 2 * tig;
                int cg = nBase + col;
                float b0 = bias[cg], b1 = bias[cg + 1];
                float2 o0, o1;
                o0.x = acc[mi][j][0] + R[r0 * 66 + col] + b0;
                o0.y = acc[mi][j][1] + R[r0 * 66 + col + 1] + b1;
                o1.x = acc[mi][j][2] + R[(r0 + 8) * 66 + col] + b0;
                o1.y = acc[mi][j][3] + R[(r0 + 8) * 66 + col + 1] + b1;
                *(float2*)&g_vis[(size_t)(mBase + r0) * HDIM + cg] = o0;
                *(float2*)&g_vis[(size_t)(mBase + r0 + 8) * HDIM + cg] = o1;
            }
        }
    }
}

// ---------------- K4: FUSED gates + gate-scale + pack-split --------------
__global__ __launch_bounds__(256) void gate_kernel(const float* __restrict__ tag,
                                                   const float* __restrict__ pos,
                                                   const float* __restrict__ Wsoft,
                                                   const float* __restrict__ bsoft) {
    int tid = threadIdx.x;
    int w = tid >> 5, lane = tid & 31;
    int rb = blockIdx.x * 4;
    int r = rb + (w >> 1);
    int half = w & 1;
    __shared__ float pl[8][2];
    __shared__ float w0s[4], w1s[4];

    {
        const float4* v = (const float4*)(g_vis + (size_t)r * HDIM);
        const float4* t = (const float4*)(tag + (size_t)r * HDIM);
        const float4* p = (const float4*)(pos + (size_t)r * HDIM);
        const float4* Wq = (const float4*)Wsoft;
        float l0 = 0.f, l1 = 0.f;
        #pragma unroll
        for (int i = 0; i < 2; i++) {
            int h4 = half * 64 + i * 32 + lane;
            float4 a = v[h4], c = t[h4], e = p[h4];
            float s0 = a.x + c.x + e.x, s1 = a.y + c.y + e.y;
            float s2 = a.z + c.z + e.z, s3 = a.w + c.w + e.w;
            float4 w01 = Wq[h4 * 2], w23 = Wq[h4 * 2 + 1];
            l0 += s0 * w01.x + s1 * w01.z + s2 * w23.x + s3 * w23.z;
            l1 += s0 * w01.y + s1 * w01.w + s2 * w23.y + s3 * w23.w;
        }
        #pragma unroll
        for (int o = 16; o; o >>= 1) {
            l0 += __shfl_xor_sync(0xffffffffu, l0, o);
            l1 += __shfl_xor_sync(0xffffffffu, l1, o);
        }
        if (lane == 0) { pl[w][0] = l0; pl[w][1] = l1; }
    }
    __syncthreads();
    if (tid < 4) {
        float L0 = pl[tid * 2][0] + pl[tid * 2 + 1][0];
        float L1 = pl[tid * 2][1] + pl[tid * 2 + 1][1];
        L0 = (L0 + bsoft[0]) / 0.03f;
        L1 = (L1 + bsoft[1]) / 0.03f;
        float m = fmaxf(L0, L1);
        float lse = m + logf(expf(L0 - m) + expf(L1 - m));
        w0s[tid] = L0 - lse;
        w1s[tid] = L1 - lse;
    }
    __syncthreads();

    int rl = tid >> 6;
    int c = tid & 63;
    int row = rb + rl;
    float w0 = w0s[rl], w1 = w1s[rl];
    const float* v = g_vis + (size_t)row * HDIM + c * 8;
    const float* t = tag + (size_t)row * HDIM + c * 8;
    float4 v0 = *(const float4*)v, v1 = *(const float4*)(v + 4);
    float4 t0 = *(const float4*)t, t1 = *(const float4*)(t + 4);
    v0.x *= w0; v0.y *= w0; v0.z *= w0; v0.w *= w0;
    v1.x *= w0; v1.y *= w0; v1.z *= w0; v1.w *= w0;
    t0.x *= w1; t0.y *= w1; t0.z *= w1; t0.w *= w1;
    t1.x *= w1; t1.y *= w1; t1.z *= w1; t1.w *= w1;
    uint4 h, l;
    split_pair(v0.x, v0.y, h.x, l.x);
    split_pair(v0.z, v0.w, h.y, l.y);
    split_pair(v1.x, v1.y, h.z, l.z);
    split_pair(v1.z, v1.w, h.w, l.w);
    *(uint4*)&g_XYH[(size_t)row * HDIM + c * 4] = h;
    *(uint4*)&g_XYL[(size_t)row * HDIM + c * 4] = l;
    split_pair(t0.x, t0.y, h.x, l.x);
    split_pair(t0.z, t0.w, h.y, l.y);
    split_pair(t1.x, t1.y, h.z, l.z);
    split_pair(t1.z, t1.w, h.w, l.w);
    *(uint4*)&g_XYH[(size_t)row * HDIM + 256 + c * 4] = h;
    *(uint4*)&g_XYL[(size_t)row * HDIM + 256 + c * 4] = l;
}

// ---------------- K5: vis2 concat-K GEMM (3x bf16) -----------------------
#define G2_NT ((2 * HDIM) / 64)
__global__ __launch_bounds__(256) void gemm2_kernel(
    const float* __restrict__ bvp, const float* __restrict__ btg,
    const float* __restrict__ pos) {
    int mBase = blockIdx.y * 32;
    int nBase = blockIdx.x * 64;
    int tid = threadIdx.x;
    int warp = tid >> 5, lane = tid & 31;
    int gid = lane >> 2, tig = lane & 3;
    int kh = warp >> 1;
    int wn = (warp & 1) * 32;
    int po = kh * 8;

    __shared__ __align__(16) uint32_t AsH[2][32 * AST];
    __shared__ __align__(16) uint32_t AsL[2][32 * AST];
    __shared__ __align__(16) uint32_t WsH[2][32 * 64];
    __shared__ __align__(16) uint32_t WsL[2][32 * 64];
    __shared__ float Red[2][32 * 66];

    int a_row = tid >> 3;
    int a_p = (tid & 7) * 4;
    int w_p = tid >> 4;
    int w_n = (tid & 15) * 4;
    int w_sw = w_n ^ ((w_p & 3) * 8);

    const uint32_t* AbH = g_XYH + (size_t)mBase * HDIM;
    const uint32_t* AbL = g_XYL + (size_t)mBase * HDIM;

    uint4 rAh, rAl, rWh[2], rWl[2];
    rAh = *(const uint4*)&AbH[(size_t)a_row * HDIM + a_p];
    rAl = *(const uint4*)&AbL[(size_t)a_row * HDIM + a_p];
    #pragma unroll
    for (int i = 0; i < 2; i++) {
        size_t off = (size_t)(w_p + i * 16) * HDIM + nBase + w_n;
        rWh[i] = *(const uint4*)&g_WcH[off];
        rWl[i] = *(const uint4*)&g_WcL[off];
    }
    *(uint4*)&AsH[0][a_row * AST + a_p] = rAh;
    *(uint4*)&AsL[0][a_row * AST + a_p] = rAl;
    #pragma unroll
    for (int i = 0; i < 2; i++) {
        int off = (w_p + i * 16) * 64 + w_sw;
        *(uint4*)&WsH[0][off] = rWh[i];
        *(uint4*)&WsL[0][off] = rWl[i];
    }
    __syncthreads();

    float acc[2][4][4];
    #pragma unroll
    for (int mi = 0; mi < 2; mi++)
        #pragma unroll
        for (int j = 0; j < 4; j++)
            #pragma unroll
            for (int r = 0; r < 4; r++) acc[mi][j][r] = 0.f;

    for (int t = 0; t < G2_NT; t++) {
        int cur = t & 1;
        if (t + 1 < G2_NT) {
            int p0n = (t + 1) * 32;
            rAh = *(const uint4*)&AbH[(size_t)a_row * HDIM + p0n + a_p];
            rAl = *(const uint4*)&AbL[(size_t)a_row * HDIM + p0n + a_p];
            #pragma unroll
            for (int i = 0; i < 2; i++) {
                size_t off = (size_t)(p0n + w_p + i * 16) * HDIM + nBase + w_n;
                rWh[i] = *(const uint4*)&g_WcH[off];
                rWl[i] = *(const uint4*)&g_WcL[off];
            }
        }
        uint32_t ah[2][4], al[2][4];
        #pragma unroll
        for (int mi = 0; mi < 2; mi++) {
            int r0 = (mi * 16 + gid) * AST + po + tig;
            ah[mi][0] = AsH[cur][r0];
            ah[mi][1] = AsH[cur][r0 + 8 * AST];
            ah[mi][2] = AsH[cur][r0 + 4];
            ah[mi][3] = AsH[cur][r0 + 8 * AST + 4];
            al[mi][0] = AsL[cur][r0];
            al[mi][1] = AsL[cur][r0 + 8 * AST];
            al[mi][2] = AsL[cur][r0 + 4];
            al[mi][3] = AsL[cur][r0 + 8 * AST + 4];
        }
        #pragma unroll
        for (int j = 0; j < 4; j++) {
            int sw = (wn + j * 8 + gid) ^ (tig * 8);
            uint32_t bh[2], bl[2];
            bh[0] = WsH[cur][(po + tig) * 64 + sw];
            bh[1] = WsH[cur][(po + tig + 4) * 64 + sw];
            bl[0] = WsL[cur][(po + tig) * 64 + sw];
            bl[1] = WsL[cur][(po + tig + 4) * 64 + sw];
            mma16(acc[0][j], ah[0], bh);
            mma16(acc[0][j], ah[0], bl);
            mma16(acc[0][j], al[0], bh);
            mma16(acc[1][j], ah[1], bh);
            mma16(acc[1][j], ah[1], bl);
            mma16(acc[1][j], al[1], bh);
        }
        if (t + 1 < G2_NT) {
            int nx = cur ^ 1;
            *(uint4*)&AsH[nx][a_row * AST + a_p] = rAh;
            *(uint4*)&AsL[nx][a_row * AST + a_p] = rAl;
            #pragma unroll
            for (int i = 0; i < 2; i++) {
                int off = (w_p + i * 16) * 64 + w_sw;
                *(uint4*)&WsH[nx][off] = rWh[i];
                *(uint4*)&WsL[nx][off] = rWl[i];
            }
        }
        __syncthreads();
    }

    if (kh >= 2) {
        float* R = Red[kh - 2];
        #pragma unroll
        for (int mi = 0; mi < 2; mi++) {
            int r0 = mi * 16 + gid;
            #pragma unroll
            for (int j = 0; j < 4; j++) {
                int col = wn + j * 8 + 2 * tig;
                R[r0 * 66 + col] = acc[mi][j][0];
                R[r0 * 66 + col + 1] = acc[mi][j][1];
                R[(r0 + 8) * 66 + col] = acc[mi][j][2];
                R[(r0 + 8) * 66 + col + 1] = acc[mi][j][3];
            }
        }
    }
    __syncthreads();
    if (kh < 2) {
        const float* R = Red[kh];
        #pragma unroll
        for (int mi = 0; mi < 2; mi++) {
            int r0 = mi * 16 + gid;
            #pragma unroll
            for (int j = 0; j < 4; j++) {
                int col = wn + j * 8 + 2 * tig;
                acc[mi][j][0] += R[r0 * 66 + col];
                acc[mi][j][1] += R[r0 * 66 + col + 1];
                acc[mi][j][2] += R[(r0 + 8) * 66 + col];
                acc[mi][j][3] += R[(r0 + 8) * 66 + col + 1];
            }
        }
    }
    __syncthreads();
    if (kh == 1) {
        float* R = Red[0];
        #pragma unroll
        for (int mi = 0; mi < 2; mi++) {
            int r0 = mi * 16 + gid;
            #pragma unroll
            for (int j = 0; j < 4; j++) {
                int col = wn + j * 8 + 2 * tig;
                R[r0 * 66 + col] = acc[mi][j][0];
                R[r0 * 66 + col + 1] = acc[mi][j][1];
                R[(r0 + 8) * 66 + col] = acc[mi][j][2];
                R[(r0 + 8) * 66 + col + 1] = acc[mi][j][3];
            }
        }
    }
    __syncthreads();
    if (kh == 0) {
        const float* R = Red[0];
        #pragma unroll
        for (int mi = 0; mi < 2; mi++) {
            int r0 = mi * 16 + gid;
            #pragma unroll
            for (int j = 0; j < 4; j++) {
                int col = wn + j * 8 + 2 * tig;
                int cg = nBase + col;
                float b0 = bvp[cg] + btg[cg];
                float b1 = bvp[cg + 1] + btg[cg + 1];
                size_t ro0 = (size_t)(mBase + r0) * HDIM + cg;
                size_t ro1 = (size_t)(mBase + r0 + 8) * HDIM + cg;
                float2 p0 = *(const float2*)&pos[ro0];
                float2 p1 = *(const float2*)&pos[ro1];
                float2 o0, o1;
                o0.x = acc[mi][j][0] + R[r0 * 66 + col] + b0 + p0.x;
                o0.y = acc[mi][j][1] + R[r0 * 66 + col + 1] + b1 + p0.y;
                o1.x = acc[mi][j][2] + R[(r0 + 8) * 66 + col] + b0 + p1.x;
                o1.y = acc[mi][j][3] + R[(r0 + 8) * 66 + col + 1] + b1 + p1.y;
                *(float2*)&g_vis2[ro0] = o0;
                *(float2*)&g_vis2[ro1] = o1;
            }
        }
    }
}

// ---------------- K6: FUSED lang proj + cosine sim + argmax + box --------
__global__ __launch_bounds__(1024) void final_kernel(
    const float* __restrict__ boxes, const float* __restrict__ lang,
    const float* __restrict__ Wts, const float* __restrict__ bts,
    float* __restrict__ out) {
    int b = blockIdx.x, tid = threadIdx.x;   // 1024 threads = 32 warps
    int w = tid >> 5, lane = tid & 31;
    __shared__ float lg[HDIM];
    __shared__ float le[HDIM];
    __shared__ float part[1024];
    __shared__ float wr[16];
    __shared__ float ssim[SEL];
    __shared__ float s_ln;

    if (tid < HDIM) lg[tid] = lang[b * HDIM + tid];
    __syncthreads();
    {
        int h = tid & (HDIM - 1);
        int khalf = tid >> 9;
        int k0 = khalf * (HDIM / 2);
        float a = 0.f;
        #pragma unroll 8
        for (int k = 0; k < HDIM / 2; k++)
            a += lg[k0 + k] * Wts[(size_t)(k0 + k) * HDIM + h];
        part[tid] = a;
    }
    __syncthreads();
    if (tid < HDIM) le[tid] = part[tid] + part[tid + HDIM] + bts[tid];
    __syncthreads();
    if (tid < HDIM) {
        float q = le[tid] * le[tid];
        #pragma unroll
        for (int o = 16; o; o >>= 1) q += __shfl_xor_sync(0xffffffffu, q, o);
        if (lane == 0) wr[w] = q;
    }
    __syncthreads();
    if (tid == 0) {
        float s = 0.f;
        #pragma unroll
        for (int i = 0; i < 16; i++) s += wr[i];
        s_ln = sqrtf(s) + EPSF;
    }
    __syncthreads();

    const float4* v2 = (const float4*)(g_vis2 + (size_t)(b * SEL + w) * HDIM);
    const float4* lef = (const float4*)le;
    float d = 0.f, q = 0.f;
    #pragma unroll
    for (int i = 0; i < 4; i++) {
        float4 a = v2[lane + i * 32];
        float4 c = lef[lane + i * 32];
        d += a.x * c.x + a.y * c.y + a.z * c.z + a.w * c.w;
        q += a.x * a.x + a.y * a.y + a.z * a.z + a.w * a.w;
    }
    #pragma unroll
    for (int o = 16; o; o >>= 1) {
        d += __shfl_xor_sync(0xffffffffu, d, o);
        q += __shfl_xor_sync(0xffffffffu, q, o);
    }
    if (lane == 0) ssim[w] = d / ((sqrtf(q) + EPSF) * s_ln);
    __syncthreads();

    if (tid < SEL) out[BS * 5 + b * SEL + tid] = ssim[tid];

    if (w == 0) {
        float v = ssim[lane]; int bi = lane;
        #pragma unroll
        for (int o = 16; o; o >>= 1) {
            float ov = __shfl_down_sync(0xffffffffu, v, o);
            int   oi = __shfl_down_sync(0xffffffffu, bi, o);
            if (ov > v || (ov == v && oi < bi)) { v = ov; bi = oi; }
        }
        if (lane == 0) {
            int g = g_idx[b * SEL + bi];
            const float* base = boxes + ((size_t)b * GRID_N + g) * A_N * CH;
            int j = 0; float ov = base[4];
            for (int a = 1; a < A_N; a++) {
                float o2 = base[a * CH + 4];
                if (o2 > ov) { ov = o2; j = a; }
            }
            float x = base[j * CH + 0], y = base[j * CH + 1];
            float wd = base[j * CH + 2], hh = base[j * CH + 3];
            float x1 = x - wd * 0.5f, y1 = y - hh * 0.5f;
            out[b * 5 + 0] = x1;
            out[b * 5 + 1] = y1;
            out[b * 5 + 2] = x1 + wd;
            out[b * 5 + 3] = y1 + hh;
            out[b * 5 + 4] = ov;
        }
    }
}

// ---------------- launch --------------------------------------------------
extern "C" void kernel_launch(void* const* d_in, const int* in_sizes, int n_in,
                              void* d_out, int out_size) {
    const float* boxes    = (const float*)d_in[0];
    const float* x_feat   = (const float*)d_in[1];
    const float* tag_emb  = (const float*)d_in[2];
    const float* pos_emb  = (const float*)d_in[3];
    const float* lang     = (const float*)d_in[4];
    const float* W_vs     = (const float*)d_in[5];
    const float* b_vs     = (const float*)d_in[6];
    const float* W_ts     = (const float*)d_in[7];
    const float* b_ts     = (const float*)d_in[8];
    const float* W_vs_pos = (const float*)d_in[9];
    const float* b_vs_pos = (const float*)d_in[10];
    const float* W_tag    = (const float*)d_in[11];
    const float* b_tag    = (const float*)d_in[12];
    const float* W_soft   = (const float*)d_in[13];
    const float* b_soft   = (const float*)d_in[14];
    float* out = (float*)d_out;

    wsplit_kernel<<<512, 256>>>(W_vs, W_vs_pos, W_tag);
    topk_kernel<<<BS, 256>>>(boxes);
    gather_kernel<<<BS * SEL, 256>>>(x_feat);
    gemm1_kernel<<<dim3(HDIM / 64, ROWS / 32), 256>>>(b_vs);
    gate_kernel<<<ROWS / 4, 256>>>(tag_emb, pos_emb, W_soft, b_soft);
    gemm2_kernel<<<dim3(HDIM / 64, ROWS / 32), 256>>>(b_vs_pos, b_tag, pos_emb);
    final_kernel<<<BS, 1024>>>(boxes, lang, W_ts, b_ts, out);
}